// round 1
// baseline (speedup 1.0000x reference)
#include <cuda_runtime.h>
#include <cuda_bf16.h>
#include <cstdint>

#define K_CLUSTERS 512
#define D_FEAT 64
#define TM 256          // points per CTA
#define NTHREADS 256
#define XSTRIDE 68      // padded row stride (floats) for x tile: 68%32=4 -> 4-way conflict only
#define INV_T 10.0f
#define LOG2E 1.4426950408889634f

// smem layout (floats):
//   c_sm  [K_CLUSTERS * D_FEAT]          = 32768 floats (128 KB)
//   b_sm  [K_CLUSTERS]                   = 512 floats   (2 KB)   b_k = |c_k|^2 * INV_T * LOG2E
//   x_sm  [TM * XSTRIDE]                 = 17408 floats (68 KB)  also reused for output staging
#define SMEM_FLOATS (K_CLUSTERS * D_FEAT + K_CLUSTERS + TM * XSTRIDE)

__device__ __forceinline__ float ex2f(float x) {
    float y;
    asm("ex2.approx.ftz.f32 %0, %1;" : "=f"(y) : "f"(x));
    return y;
}

__global__ void __launch_bounds__(NTHREADS, 1)
kmeans_mixture_kernel(const float* __restrict__ x,
                      const float* __restrict__ centroids,
                      float* __restrict__ out,
                      int n_points)
{
    extern __shared__ float smem[];
    float* c_sm = smem;
    float* b_sm = smem + K_CLUSTERS * D_FEAT;
    float* x_sm = b_sm + K_CLUSTERS;

    const int tid = threadIdx.x;

    // ---- load centroids (coalesced, float4) ----
    {
        const float4* src = reinterpret_cast<const float4*>(centroids);
        float4* dst = reinterpret_cast<float4*>(c_sm);
        const int nvec = K_CLUSTERS * D_FEAT / 4;  // 8192
        #pragma unroll
        for (int i = 0; i < nvec / NTHREADS; i++) {
            dst[tid + i * NTHREADS] = src[tid + i * NTHREADS];
        }
    }
    __syncthreads();

    // ---- precompute bias b_k = |c_k|^2 * INV_T * LOG2E ----
    #pragma unroll
    for (int kk = 0; kk < K_CLUSTERS / NTHREADS; kk++) {
        const int k = tid + kk * NTHREADS;
        const float* c = &c_sm[k * D_FEAT];
        float s0 = 0.f, s1 = 0.f, s2 = 0.f, s3 = 0.f;
        #pragma unroll
        for (int d = 0; d < D_FEAT; d += 4) {
            s0 += c[d + 0] * c[d + 0];
            s1 += c[d + 1] * c[d + 1];
            s2 += c[d + 2] * c[d + 2];
            s3 += c[d + 3] * c[d + 3];
        }
        b_sm[k] = ((s0 + s1) + (s2 + s3)) * (INV_T * LOG2E);
    }

    // ---- load x tile (coalesced) into padded smem rows ----
    const long base = (long)blockIdx.x * TM;
    const int rows = (int)min((long)TM, (long)n_points - base);
    {
        const float* xg = x + base * D_FEAT;
        const int total = rows * D_FEAT;
        for (int i = tid; i < total; i += NTHREADS) {
            const int r = i >> 6;          // /64
            const int c = i & 63;
            x_sm[r * XSTRIDE + c] = xg[i];
        }
    }
    __syncthreads();

    // ---- per-thread point ----
    const int p = tid;
    float xr[D_FEAT];
    float acc[D_FEAT];
    float ssum = 0.f;

    if (p < rows) {
        const float4* xrow = reinterpret_cast<const float4*>(&x_sm[p * XSTRIDE]);
        #pragma unroll
        for (int d = 0; d < D_FEAT / 4; d++) {
            float4 v = xrow[d];
            xr[4 * d + 0] = v.x; xr[4 * d + 1] = v.y;
            xr[4 * d + 2] = v.z; xr[4 * d + 3] = v.w;
        }
        #pragma unroll
        for (int d = 0; d < D_FEAT; d++) acc[d] = 0.f;

        const float A = 2.0f * INV_T * LOG2E;

        #pragma unroll 1
        for (int k = 0; k < K_CLUSTERS; k++) {
            const float* c = &c_sm[k * D_FEAT];
            // dot product, 4 partials
            float d0 = 0.f, d1 = 0.f, d2 = 0.f, d3 = 0.f;
            #pragma unroll
            for (int d = 0; d < D_FEAT; d += 4) {
                d0 = fmaf(xr[d + 0], c[d + 0], d0);
                d1 = fmaf(xr[d + 1], c[d + 1], d1);
                d2 = fmaf(xr[d + 2], c[d + 2], d2);
                d3 = fmaf(xr[d + 3], c[d + 3], d3);
            }
            const float dot = (d0 + d1) + (d2 + d3);
            const float w = ex2f(fmaf(dot, A, -b_sm[k]));
            ssum += w;
            #pragma unroll
            for (int d = 0; d < D_FEAT; d++) {
                acc[d] = fmaf(w, c[d], acc[d]);
            }
        }
    }
    __syncthreads();  // done reading x_sm; reuse it for output staging

    if (p < rows) {
        const float inv = __frcp_rn(ssum);
        float4* orow = reinterpret_cast<float4*>(&x_sm[p * XSTRIDE]);
        #pragma unroll
        for (int d = 0; d < D_FEAT / 4; d++) {
            float4 v;
            v.x = acc[4 * d + 0] * inv;
            v.y = acc[4 * d + 1] * inv;
            v.z = acc[4 * d + 2] * inv;
            v.w = acc[4 * d + 3] * inv;
            orow[d] = v;
        }
    }
    __syncthreads();

    // ---- coalesced store ----
    {
        float* og = out + base * D_FEAT;
        const int total = rows * D_FEAT;
        for (int i = tid; i < total; i += NTHREADS) {
            const int r = i >> 6;
            const int c = i & 63;
            og[i] = x_sm[r * XSTRIDE + c];
        }
    }
}

extern "C" void kernel_launch(void* const* d_in, const int* in_sizes, int n_in,
                              void* d_out, int out_size)
{
    const float* x = (const float*)d_in[0];
    const float* centroids = (const float*)d_in[1];
    float* out = (float*)d_out;

    const int n_points = in_sizes[0] / D_FEAT;  // 131072
    const int smem_bytes = SMEM_FLOATS * (int)sizeof(float);

    static bool attr_set = false;
    if (!attr_set) {
        cudaFuncSetAttribute(kmeans_mixture_kernel,
                             cudaFuncAttributeMaxDynamicSharedMemorySize, smem_bytes);
        attr_set = true;
    }

    const int grid = (n_points + TM - 1) / TM;
    kmeans_mixture_kernel<<<grid, NTHREADS, smem_bytes>>>(x, centroids, out, n_points);
}

// round 2
// speedup vs baseline: 1.0642x; 1.0642x over previous
#include <cuda_runtime.h>
#include <cuda_bf16.h>
#include <cstdint>

#define K_CLUSTERS 512
#define D_FEAT 64
#define TM 256          // points per CTA
#define NTHREADS 256
#define XSTRIDE 68      // padded row stride (floats); 272B, 16B-aligned
#define INV_T 10.0f
#define LOG2E 1.4426950408889634f

#define SMEM_FLOATS (K_CLUSTERS * D_FEAT + K_CLUSTERS + TM * XSTRIDE)

typedef unsigned long long u64;

__device__ __forceinline__ float ex2f(float x) {
    float y;
    asm("ex2.approx.ftz.f32 %0, %1;" : "=f"(y) : "f"(x));
    return y;
}
__device__ __forceinline__ u64 pack2(float lo, float hi) {
    u64 r;
    asm("mov.b64 %0, {%1, %2};" : "=l"(r) : "f"(lo), "f"(hi));
    return r;
}
__device__ __forceinline__ void unpack2(u64 v, float& lo, float& hi) {
    asm("mov.b64 {%0, %1}, %2;" : "=f"(lo), "=f"(hi) : "l"(v));
}
// packed dual-FMA: d = a*b + c elementwise on f32x2 (sm_103a FFMA2)
__device__ __forceinline__ u64 ffma2(u64 a, u64 b, u64 c) {
    u64 d;
    asm("fma.rn.f32x2 %0, %1, %2, %3;" : "=l"(d) : "l"(a), "l"(b), "l"(c));
    return d;
}

__global__ void __launch_bounds__(NTHREADS, 1)
kmeans_mixture_kernel(const float* __restrict__ x,
                      const float* __restrict__ centroids,
                      float* __restrict__ out,
                      int n_points)
{
    extern __shared__ float smem[];
    float* c_sm = smem;
    float* b_sm = smem + K_CLUSTERS * D_FEAT;
    float* x_sm = b_sm + K_CLUSTERS;

    const int tid = threadIdx.x;

    // ---- load centroids (coalesced, float4) ----
    {
        const float4* src = reinterpret_cast<const float4*>(centroids);
        float4* dst = reinterpret_cast<float4*>(c_sm);
        const int nvec = K_CLUSTERS * D_FEAT / 4;  // 8192
        #pragma unroll
        for (int i = 0; i < nvec / NTHREADS; i++) {
            dst[tid + i * NTHREADS] = src[tid + i * NTHREADS];
        }
    }
    __syncthreads();

    // ---- precompute bias b_k = |c_k|^2 * INV_T * LOG2E ----
    #pragma unroll
    for (int kk = 0; kk < K_CLUSTERS / NTHREADS; kk++) {
        const int k = tid + kk * NTHREADS;
        const float* c = &c_sm[k * D_FEAT];
        float s0 = 0.f, s1 = 0.f, s2 = 0.f, s3 = 0.f;
        #pragma unroll
        for (int d = 0; d < D_FEAT; d += 4) {
            s0 += c[d + 0] * c[d + 0];
            s1 += c[d + 1] * c[d + 1];
            s2 += c[d + 2] * c[d + 2];
            s3 += c[d + 3] * c[d + 3];
        }
        b_sm[k] = ((s0 + s1) + (s2 + s3)) * (INV_T * LOG2E);
    }

    // ---- load x tile (coalesced) into padded smem rows ----
    const long base = (long)blockIdx.x * TM;
    const int rows = (int)min((long)TM, (long)n_points - base);
    {
        const float* xg = x + base * D_FEAT;
        const int total = rows * D_FEAT;
        for (int i = tid; i < total; i += NTHREADS) {
            const int r = i >> 6;          // /64
            const int c = i & 63;
            x_sm[r * XSTRIDE + c] = xg[i];
        }
    }
    __syncthreads();

    // ---- per-thread point: packed f32x2 math ----
    const int p = tid;
    u64 X[D_FEAT / 2];     // x row, 32 packed pairs
    u64 A[D_FEAT / 2];     // mixture accumulator, 32 packed pairs
    float ssum = 0.f;

    if (p < rows) {
        const u64* xrow = reinterpret_cast<const u64*>(&x_sm[p * XSTRIDE]);
        #pragma unroll
        for (int j = 0; j < D_FEAT / 2; j++) X[j] = xrow[j];

        const u64 Z = pack2(0.f, 0.f);
        #pragma unroll
        for (int j = 0; j < D_FEAT / 2; j++) A[j] = Z;

        const float SC = 2.0f * INV_T * LOG2E;   // logit scale in log2 units

        #pragma unroll 2
        for (int k = 0; k < K_CLUSTERS; k++) {
            const u64* c2 = reinterpret_cast<const u64*>(&c_sm[k * D_FEAT]);
            // packed dot product: 4 independent packed partials
            u64 p0 = Z, p1 = Z, p2 = Z, p3 = Z;
            #pragma unroll
            for (int j = 0; j < D_FEAT / 2; j += 4) {
                p0 = ffma2(X[j + 0], c2[j + 0], p0);
                p1 = ffma2(X[j + 1], c2[j + 1], p1);
                p2 = ffma2(X[j + 2], c2[j + 2], p2);
                p3 = ffma2(X[j + 3], c2[j + 3], p3);
            }
            float a0, a1, b0, b1, e0, e1, f0, f1;
            unpack2(p0, a0, a1);
            unpack2(p1, b0, b1);
            unpack2(p2, e0, e1);
            unpack2(p3, f0, f1);
            const float dot = ((a0 + a1) + (b0 + b1)) + ((e0 + e1) + (f0 + f1));

            const float w = ex2f(fmaf(dot, SC, -b_sm[k]));
            ssum += w;
            const u64 w2 = pack2(w, w);
            #pragma unroll
            for (int j = 0; j < D_FEAT / 2; j++) {
                A[j] = ffma2(w2, c2[j], A[j]);
            }
        }
    }
    __syncthreads();  // done reading x_sm; reuse it for output staging

    if (p < rows) {
        const float inv = __frcp_rn(ssum);
        float* orow = &x_sm[p * XSTRIDE];
        #pragma unroll
        for (int j = 0; j < D_FEAT / 2; j++) {
            float lo, hi;
            unpack2(A[j], lo, hi);
            orow[2 * j + 0] = lo * inv;
            orow[2 * j + 1] = hi * inv;
        }
    }
    __syncthreads();

    // ---- coalesced store ----
    {
        float* og = out + base * D_FEAT;
        const int total = rows * D_FEAT;
        for (int i = tid; i < total; i += NTHREADS) {
            const int r = i >> 6;
            const int c = i & 63;
            og[i] = x_sm[r * XSTRIDE + c];
        }
    }
}

extern "C" void kernel_launch(void* const* d_in, const int* in_sizes, int n_in,
                              void* d_out, int out_size)
{
    const float* x = (const float*)d_in[0];
    const float* centroids = (const float*)d_in[1];
    float* out = (float*)d_out;

    const int n_points = in_sizes[0] / D_FEAT;  // 131072
    const int smem_bytes = SMEM_FLOATS * (int)sizeof(float);

    static bool attr_set = false;
    if (!attr_set) {
        cudaFuncSetAttribute(kmeans_mixture_kernel,
                             cudaFuncAttributeMaxDynamicSharedMemorySize, smem_bytes);
        attr_set = true;
    }

    const int grid = (n_points + TM - 1) / TM;
    kmeans_mixture_kernel<<<grid, NTHREADS, smem_bytes>>>(x, centroids, out, n_points);
}

// round 5
// speedup vs baseline: 2.9223x; 2.7460x over previous
#include <cuda_runtime.h>
#include <cuda_bf16.h>
#include <cstdint>

#define D_FEAT 64
#define TILE_M 128
#define NTHREADS 256
#define INV_T 10.0f
#define LOG2E 1.4426950408889634f
#define HALF_K 256
#define MAXTILES 7

// smem byte offsets
#define SM_CHI 0           // K-major C hi   [256 cl x 128B]  32KB
#define SM_CLO 32768       // K-major C lo                    32KB
#define SM_CTHI 65536      // feat-major C^T hi [64 f x 512B] 32KB
#define SM_CTLO 98304      // feat-major C^T lo               32KB
#define SM_BIAS 131072     // 256 floats                      1KB
#define SM_SSUM 132096     // MAXTILES*128 floats             3.5KB
#define SM_TOTAL 135680

#define SWZ(x)    ((x) ^ (((x) >> 3) & 0x70))
#define SWZ512(x) ((x) ^ (((x) >> 5) & 0x70))

typedef unsigned int u32;

__device__ __forceinline__ float ex2f(float v) {
    float y; asm("ex2.approx.ftz.f32 %0, %1;" : "=f"(y) : "f"(v)); return y;
}
// pack (lo, hi) -> bf16x2 with lo in low half
__device__ __forceinline__ u32 bf2(float lo, float hi) {
    u32 r; asm("cvt.rn.satfinite.bf16x2.f32 %0, %1, %2;" : "=r"(r) : "f"(hi), "f"(lo)); return r;
}
__device__ __forceinline__ float2 unbf2(u32 v) {
    __nv_bfloat162 b = *reinterpret_cast<__nv_bfloat162*>(&v);
    return make_float2(__bfloat162float(b.x), __bfloat162float(b.y));
}
// hi split + residual lo split
__device__ __forceinline__ u32 bf2r(float a, float b, u32& lo) {
    const u32 h = bf2(a, b);
    const float2 f = unbf2(h);
    lo = bf2(a - f.x, b - f.y);
    return h;
}
// D += A*B, m16n8k16 bf16 -> f32
__device__ __forceinline__ void mma16816(float* d, const u32* a, u32 b0, u32 b1) {
    asm volatile("mma.sync.aligned.m16n8k16.row.col.f32.bf16.bf16.f32 "
                 "{%0,%1,%2,%3}, {%4,%5,%6,%7}, {%8,%9}, {%0,%1,%2,%3};"
                 : "+f"(d[0]), "+f"(d[1]), "+f"(d[2]), "+f"(d[3])
                 : "r"(a[0]), "r"(a[1]), "r"(a[2]), "r"(a[3]), "r"(b0), "r"(b1));
}

__global__ void __launch_bounds__(NTHREADS, 1)
kmeans_hmma2_kernel(const float* __restrict__ x,
                    const float* __restrict__ centroids,
                    float* __restrict__ out,
                    int n_tiles)
{
    extern __shared__ char smem[];
    const int tid = threadIdx.x;
    const int lane = tid & 31;
    const int wid = tid >> 5;
    const int gid = lane >> 2;      // fragment row group 0..7
    const int tg = lane & 3;        // thread in group
    const int m0 = wid * 16;        // warp's 16-row block

    const float SC = 2.0f * INV_T * LOG2E;

    #pragma unroll 1
    for (int h = 0; h < 2; h++) {
        __syncthreads();   // everyone done with previous half's C smem
        // ---- build half h: K-major C hi/lo, feat-major C^T hi/lo, bias ----
        {
            const float4* C4 = reinterpret_cast<const float4*>(centroids) +
                               (size_t)h * HALF_K * (D_FEAT / 4);
            const float BSCALE = INV_T * LOG2E;
            #pragma unroll 1
            for (int it = 0; it < 16; it++) {
                const int i = tid + it * NTHREADS;     // 0..4095
                const float4 v = C4[i];
                const int cl = i >> 4;                 // local cluster 0..255
                const int dq = i & 15;                 // float4 index in row
                u32 l0, l1;
                const u32 h0 = bf2r(v.x, v.y, l0);
                const u32 h1 = bf2r(v.z, v.w, l1);
                const u32 off = SWZ((u32)(cl * 128 + dq * 8));
                *reinterpret_cast<uint2*>(smem + SM_CHI + off) = make_uint2(h0, h1);
                *reinterpret_cast<uint2*>(smem + SM_CLO + off) = make_uint2(l0, l1);
                // transposed copies (2B scattered stores; prologue-only)
                const u32 ct = (u32)cl * 2;
                const __nv_bfloat162 H0 = *reinterpret_cast<const __nv_bfloat162*>(&h0);
                const __nv_bfloat162 H1 = *reinterpret_cast<const __nv_bfloat162*>(&h1);
                const __nv_bfloat162 L0 = *reinterpret_cast<const __nv_bfloat162*>(&l0);
                const __nv_bfloat162 L1 = *reinterpret_cast<const __nv_bfloat162*>(&l1);
                *reinterpret_cast<__nv_bfloat16*>(smem + SM_CTHI + SWZ512((u32)(4*dq+0)*512 + ct)) = H0.x;
                *reinterpret_cast<__nv_bfloat16*>(smem + SM_CTHI + SWZ512((u32)(4*dq+1)*512 + ct)) = H0.y;
                *reinterpret_cast<__nv_bfloat16*>(smem + SM_CTHI + SWZ512((u32)(4*dq+2)*512 + ct)) = H1.x;
                *reinterpret_cast<__nv_bfloat16*>(smem + SM_CTHI + SWZ512((u32)(4*dq+3)*512 + ct)) = H1.y;
                *reinterpret_cast<__nv_bfloat16*>(smem + SM_CTLO + SWZ512((u32)(4*dq+0)*512 + ct)) = L0.x;
                *reinterpret_cast<__nv_bfloat16*>(smem + SM_CTLO + SWZ512((u32)(4*dq+1)*512 + ct)) = L0.y;
                *reinterpret_cast<__nv_bfloat16*>(smem + SM_CTLO + SWZ512((u32)(4*dq+2)*512 + ct)) = L1.x;
                *reinterpret_cast<__nv_bfloat16*>(smem + SM_CTLO + SWZ512((u32)(4*dq+3)*512 + ct)) = L1.y;
                // bias
                float p = v.x * v.x + v.y * v.y + v.z * v.z + v.w * v.w;
                p += __shfl_xor_sync(0xFFFFFFFF, p, 1);
                p += __shfl_xor_sync(0xFFFFFFFF, p, 2);
                p += __shfl_xor_sync(0xFFFFFFFF, p, 4);
                p += __shfl_xor_sync(0xFFFFFFFF, p, 8);
                if ((lane & 15) == 0)
                    *reinterpret_cast<float*>(smem + SM_BIAS + cl * 4) = p * BSCALE;
            }
        }
        __syncthreads();

        // ---- tile loop (same tiles in both halves -> no cross-CTA deps) ----
        int tloc = 0;
        #pragma unroll 1
        for (int tile = blockIdx.x; tile < n_tiles; tile += gridDim.x, tloc++) {
            // A fragments for X: direct from gmem per PTX spec positions
            u32 Ah[4][4], Al[4][4];
            {
                const float* xb = x + ((size_t)tile * TILE_M + m0 + gid) * D_FEAT;
                #pragma unroll
                for (int s = 0; s < 4; s++) {
                    const int c0 = 16 * s + 2 * tg;
                    const float2 v0 = *reinterpret_cast<const float2*>(xb + c0);
                    const float2 v1 = *reinterpret_cast<const float2*>(xb + 8 * D_FEAT + c0);
                    const float2 v2 = *reinterpret_cast<const float2*>(xb + c0 + 8);
                    const float2 v3 = *reinterpret_cast<const float2*>(xb + 8 * D_FEAT + c0 + 8);
                    Ah[s][0] = bf2r(v0.x, v0.y, Al[s][0]);
                    Ah[s][1] = bf2r(v1.x, v1.y, Al[s][1]);
                    Ah[s][2] = bf2r(v2.x, v2.y, Al[s][2]);
                    Ah[s][3] = bf2r(v3.x, v3.y, Al[s][3]);
                }
            }

            float O[8][4];
            #pragma unroll
            for (int n = 0; n < 8; n++)
                #pragma unroll
                for (int e = 0; e < 4; e++) O[n][e] = 0.f;
            float sum0 = 0.f, sum1 = 0.f;

            #pragma unroll 1
            for (int sub = 0; sub < 4; sub++) {      // 64-cluster sub-chunks
                float S[8][4];
                #pragma unroll
                for (int n = 0; n < 8; n++)
                    #pragma unroll
                    for (int e = 0; e < 4; e++) S[n][e] = 0.f;

                // GEMM1: S = X @ C^T (3-term split), B frags per spec from K-major C
                #pragma unroll
                for (int s = 0; s < 4; s++) {
                    #pragma unroll
                    for (int nb = 0; nb < 8; nb++) {
                        const u32 cl = (u32)(sub * 64 + nb * 8 + gid);
                        const u32 base = cl * 128 + (u32)(16 * s + 2 * tg) * 2;
                        const u32 a0 = SWZ(base), a1 = SWZ(base + 16);
                        const u32 b0h = *reinterpret_cast<const u32*>(smem + SM_CHI + a0);
                        const u32 b1h = *reinterpret_cast<const u32*>(smem + SM_CHI + a1);
                        const u32 b0l = *reinterpret_cast<const u32*>(smem + SM_CLO + a0);
                        const u32 b1l = *reinterpret_cast<const u32*>(smem + SM_CLO + a1);
                        mma16816(S[nb], Ah[s], b0h, b1h);
                        mma16816(S[nb], Ah[s], b0l, b1l);
                        mma16816(S[nb], Al[s], b0h, b1h);
                    }
                }

                // epilogue: logits -> weights
                #pragma unroll
                for (int nb = 0; nb < 8; nb++) {
                    const int coll = sub * 64 + nb * 8 + 2 * tg;
                    const float2 bb = *reinterpret_cast<const float2*>(smem + SM_BIAS + coll * 4);
                    S[nb][0] = ex2f(fmaf(S[nb][0], SC, -bb.x));
                    S[nb][1] = ex2f(fmaf(S[nb][1], SC, -bb.y));
                    S[nb][2] = ex2f(fmaf(S[nb][2], SC, -bb.x));
                    S[nb][3] = ex2f(fmaf(S[nb][3], SC, -bb.y));
                    sum0 += S[nb][0] + S[nb][1];
                    sum1 += S[nb][2] + S[nb][3];
                }

                // GEMM2: O += W @ C, A = W via accum->A chaining, B from feat-major C^T
                #pragma unroll
                for (int t = 0; t < 4; t++) {
                    u32 Wh[4], Wl[4];
                    Wh[0] = bf2r(S[2*t][0],   S[2*t][1],   Wl[0]);
                    Wh[1] = bf2r(S[2*t][2],   S[2*t][3],   Wl[1]);
                    Wh[2] = bf2r(S[2*t+1][0], S[2*t+1][1], Wl[2]);
                    Wh[3] = bf2r(S[2*t+1][2], S[2*t+1][3], Wl[3]);
                    const u32 kb = (u32)(128 * sub + 32 * t + 4 * tg);
                    #pragma unroll
                    for (int nb2 = 0; nb2 < 8; nb2++) {
                        const u32 feat = (u32)(nb2 * 8 + gid);
                        const u32 base = feat * 512 + kb;
                        const u32 a0 = SWZ512(base), a1 = SWZ512(base + 16);
                        const u32 b0h = *reinterpret_cast<const u32*>(smem + SM_CTHI + a0);
                        const u32 b1h = *reinterpret_cast<const u32*>(smem + SM_CTHI + a1);
                        const u32 b0l = *reinterpret_cast<const u32*>(smem + SM_CTLO + a0);
                        const u32 b1l = *reinterpret_cast<const u32*>(smem + SM_CTLO + a1);
                        mma16816(O[nb2], Wh, b0h, b1h);
                        mma16816(O[nb2], Wh, b0l, b1l);
                        mma16816(O[nb2], Wl, b0h, b1h);
                    }
                }
            }

            // row sums across the 4 lanes of each row group
            sum0 += __shfl_xor_sync(0xFFFFFFFF, sum0, 1);
            sum0 += __shfl_xor_sync(0xFFFFFFFF, sum0, 2);
            sum1 += __shfl_xor_sync(0xFFFFFFFF, sum1, 1);
            sum1 += __shfl_xor_sync(0xFFFFFFFF, sum1, 2);

            float* op = out + ((size_t)tile * TILE_M) * D_FEAT;
            const int r0 = m0 + gid;
            const int r1 = r0 + 8;
            float* ss = reinterpret_cast<float*>(smem + SM_SSUM) + tloc * TILE_M;

            if (h == 0) {
                if (tg == 0) { ss[r0] = sum0; ss[r1] = sum1; }
                #pragma unroll
                for (int n = 0; n < 8; n++) {
                    const int col = 8 * n + 2 * tg;
                    *reinterpret_cast<float2*>(op + r0 * D_FEAT + col) = make_float2(O[n][0], O[n][1]);
                    *reinterpret_cast<float2*>(op + r1 * D_FEAT + col) = make_float2(O[n][2], O[n][3]);
                }
            } else {
                const float inv0 = __frcp_rn(sum0 + ss[r0]);
                const float inv1 = __frcp_rn(sum1 + ss[r1]);
                #pragma unroll
                for (int n = 0; n < 8; n++) {
                    const int col = 8 * n + 2 * tg;
                    float2 p0 = *reinterpret_cast<float2*>(op + r0 * D_FEAT + col);
                    float2 p1 = *reinterpret_cast<float2*>(op + r1 * D_FEAT + col);
                    *reinterpret_cast<float2*>(op + r0 * D_FEAT + col) =
                        make_float2((p0.x + O[n][0]) * inv0, (p0.y + O[n][1]) * inv0);
                    *reinterpret_cast<float2*>(op + r1 * D_FEAT + col) =
                        make_float2((p1.x + O[n][2]) * inv1, (p1.y + O[n][3]) * inv1);
                }
            }
        }
    }
}

extern "C" void kernel_launch(void* const* d_in, const int* in_sizes, int n_in,
                              void* d_out, int out_size)
{
    const float* x = (const float*)d_in[0];
    const float* centroids = (const float*)d_in[1];
    float* out = (float*)d_out;

    const int n_points = in_sizes[0] / D_FEAT;   // 131072
    const int n_tiles = n_points / TILE_M;       // 1024

    static bool attr_set = false;
    if (!attr_set) {
        cudaFuncSetAttribute(kmeans_hmma2_kernel,
                             cudaFuncAttributeMaxDynamicSharedMemorySize, SM_TOTAL);
        attr_set = true;
    }

    const int grid = (n_tiles < 148) ? n_tiles : 148;
    kmeans_hmma2_kernel<<<grid, NTHREADS, SM_TOTAL>>>(x, centroids, out, n_tiles);
}

// round 6
// speedup vs baseline: 3.2335x; 1.1065x over previous
#include <cuda_runtime.h>
#include <cuda_bf16.h>
#include <cstdint>

#define D_FEAT 64
#define TILE_M 128
#define NTHREADS 256
#define INV_T 10.0f
#define LOG2E 1.4426950408889634f
#define HALF_K 256
#define MAXTILES 7

// smem byte offsets
#define SM_CHI 0           // K-major C hi   [256 cl x 128B]  32KB
#define SM_CLO 32768       // K-major C lo                    32KB
#define SM_CTHI 65536      // feat-major C^T hi [64 f x 512B] 32KB
#define SM_CTLO 98304      // feat-major C^T lo               32KB
#define SM_BIAS 131072     // 256 floats                      1KB
#define SM_SSUM 132096     // MAXTILES*128 floats             3.5KB
#define SM_TOTAL 135680

#define SWZ(x)    ((x) ^ (((x) >> 3) & 0x70))
#define SWZ512(x) ((x) ^ (((x) >> 5) & 0x70))

typedef unsigned int u32;

__device__ __forceinline__ u32 s2u(const void* p) {
    u32 a;
    asm("{ .reg .u64 t; cvta.to.shared.u64 t, %1; cvt.u32.u64 %0, t; }" : "=r"(a) : "l"(p));
    return a;
}
__device__ __forceinline__ u32 lds32(u32 addr) {
    u32 v;
    asm volatile("ld.shared.b32 %0, [%1];" : "=r"(v) : "r"(addr));
    return v;
}
__device__ __forceinline__ float ex2f(float v) {
    float y; asm("ex2.approx.ftz.f32 %0, %1;" : "=f"(y) : "f"(v)); return y;
}
// pack (lo, hi) -> bf16x2 with lo in low half
__device__ __forceinline__ u32 bf2(float lo, float hi) {
    u32 r; asm("cvt.rn.satfinite.bf16x2.f32 %0, %1, %2;" : "=r"(r) : "f"(hi), "f"(lo)); return r;
}
__device__ __forceinline__ float2 unbf2(u32 v) {
    __nv_bfloat162 b = *reinterpret_cast<__nv_bfloat162*>(&v);
    return make_float2(__bfloat162float(b.x), __bfloat162float(b.y));
}
// hi split + residual lo split
__device__ __forceinline__ u32 bf2r(float a, float b, u32& lo) {
    const u32 h = bf2(a, b);
    const float2 f = unbf2(h);
    lo = bf2(a - f.x, b - f.y);
    return h;
}
// D += A*B, m16n8k16 bf16 -> f32
__device__ __forceinline__ void mma16816(float* d, const u32* a, u32 b0, u32 b1) {
    asm volatile("mma.sync.aligned.m16n8k16.row.col.f32.bf16.bf16.f32 "
                 "{%0,%1,%2,%3}, {%4,%5,%6,%7}, {%8,%9}, {%0,%1,%2,%3};"
                 : "+f"(d[0]), "+f"(d[1]), "+f"(d[2]), "+f"(d[3])
                 : "r"(a[0]), "r"(a[1]), "r"(a[2]), "r"(a[3]), "r"(b0), "r"(b1));
}

__global__ void __launch_bounds__(NTHREADS, 1)
kmeans_hmma3_kernel(const float* __restrict__ x,
                    const float* __restrict__ centroids,
                    float* __restrict__ out,
                    int n_tiles)
{
    extern __shared__ char smem[];
    const u32 sb = s2u(smem);
    const int tid = threadIdx.x;
    const int lane = tid & 31;
    const int wid = tid >> 5;
    const int gid = lane >> 2;      // fragment row group 0..7
    const int tg = lane & 3;        // thread in group
    const int m0 = wid * 16;        // warp's 16-row block

    const float SC = 2.0f * INV_T * LOG2E;

    // ---- loop-invariant swizzled base addresses (XOR operand is gid<<4, a
    //      per-thread constant; sub/nb offsets are purely additive) ----
    u32 g1[4][2], g2[4][2];
    #pragma unroll
    for (int s = 0; s < 4; s++) {
        #pragma unroll
        for (int j = 0; j < 2; j++) {
            g1[s][j] = sb + SM_CHI + (u32)gid * 128 +
                       (((u32)(32 * s + 4 * tg + 16 * j)) ^ ((u32)gid << 4));
            g2[s][j] = sb + SM_CTHI + (u32)gid * 512 +
                       (((u32)(32 * s + 4 * tg + 16 * j)) ^ ((u32)gid << 4));
        }
    }

    #pragma unroll 1
    for (int h = 0; h < 2; h++) {
        __syncthreads();   // everyone done with previous half's C smem
        // ---- build half h: K-major C hi/lo, feat-major C^T hi/lo, bias ----
        {
            const float4* C4 = reinterpret_cast<const float4*>(centroids) +
                               (size_t)h * HALF_K * (D_FEAT / 4);
            const float BSCALE = INV_T * LOG2E;
            #pragma unroll 1
            for (int it = 0; it < 16; it++) {
                const int i = tid + it * NTHREADS;     // 0..4095
                const float4 v = C4[i];
                const int cl = i >> 4;                 // local cluster 0..255
                const int dq = i & 15;                 // float4 index in row
                u32 l0, l1;
                const u32 h0 = bf2r(v.x, v.y, l0);
                const u32 h1 = bf2r(v.z, v.w, l1);
                const u32 off = SWZ((u32)(cl * 128 + dq * 8));
                *reinterpret_cast<uint2*>(smem + SM_CHI + off) = make_uint2(h0, h1);
                *reinterpret_cast<uint2*>(smem + SM_CLO + off) = make_uint2(l0, l1);
                // transposed copies (2B scattered stores; prologue-only)
                const u32 ct = (u32)cl * 2;
                const __nv_bfloat162 H0 = *reinterpret_cast<const __nv_bfloat162*>(&h0);
                const __nv_bfloat162 H1 = *reinterpret_cast<const __nv_bfloat162*>(&h1);
                const __nv_bfloat162 L0 = *reinterpret_cast<const __nv_bfloat162*>(&l0);
                const __nv_bfloat162 L1 = *reinterpret_cast<const __nv_bfloat162*>(&l1);
                *reinterpret_cast<__nv_bfloat16*>(smem + SM_CTHI + SWZ512((u32)(4*dq+0)*512 + ct)) = H0.x;
                *reinterpret_cast<__nv_bfloat16*>(smem + SM_CTHI + SWZ512((u32)(4*dq+1)*512 + ct)) = H0.y;
                *reinterpret_cast<__nv_bfloat16*>(smem + SM_CTHI + SWZ512((u32)(4*dq+2)*512 + ct)) = H1.x;
                *reinterpret_cast<__nv_bfloat16*>(smem + SM_CTHI + SWZ512((u32)(4*dq+3)*512 + ct)) = H1.y;
                *reinterpret_cast<__nv_bfloat16*>(smem + SM_CTLO + SWZ512((u32)(4*dq+0)*512 + ct)) = L0.x;
                *reinterpret_cast<__nv_bfloat16*>(smem + SM_CTLO + SWZ512((u32)(4*dq+1)*512 + ct)) = L0.y;
                *reinterpret_cast<__nv_bfloat16*>(smem + SM_CTLO + SWZ512((u32)(4*dq+2)*512 + ct)) = L1.x;
                *reinterpret_cast<__nv_bfloat16*>(smem + SM_CTLO + SWZ512((u32)(4*dq+3)*512 + ct)) = L1.y;
                // bias
                float p = v.x * v.x + v.y * v.y + v.z * v.z + v.w * v.w;
                p += __shfl_xor_sync(0xFFFFFFFF, p, 1);
                p += __shfl_xor_sync(0xFFFFFFFF, p, 2);
                p += __shfl_xor_sync(0xFFFFFFFF, p, 4);
                p += __shfl_xor_sync(0xFFFFFFFF, p, 8);
                if ((lane & 15) == 0)
                    *reinterpret_cast<float*>(smem + SM_BIAS + cl * 4) = p * BSCALE;
            }
        }
        __syncthreads();

        // ---- tile loop (same tiles in both halves -> no cross-CTA deps) ----
        int tloc = 0;
        #pragma unroll 1
        for (int tile = blockIdx.x; tile < n_tiles; tile += gridDim.x, tloc++) {
            // A fragments for X: direct from gmem per PTX spec positions
            u32 Ah[4][4], Al[4][4];
            {
                const float* xb = x + ((size_t)tile * TILE_M + m0 + gid) * D_FEAT;
                #pragma unroll
                for (int s = 0; s < 4; s++) {
                    const int c0 = 16 * s + 2 * tg;
                    const float2 v0 = *reinterpret_cast<const float2*>(xb + c0);
                    const float2 v1 = *reinterpret_cast<const float2*>(xb + 8 * D_FEAT + c0);
                    const float2 v2 = *reinterpret_cast<const float2*>(xb + c0 + 8);
                    const float2 v3 = *reinterpret_cast<const float2*>(xb + 8 * D_FEAT + c0 + 8);
                    Ah[s][0] = bf2r(v0.x, v0.y, Al[s][0]);
                    Ah[s][1] = bf2r(v1.x, v1.y, Al[s][1]);
                    Ah[s][2] = bf2r(v2.x, v2.y, Al[s][2]);
                    Ah[s][3] = bf2r(v3.x, v3.y, Al[s][3]);
                }
            }

            float O[8][4];
            #pragma unroll
            for (int n = 0; n < 8; n++)
                #pragma unroll
                for (int e = 0; e < 4; e++) O[n][e] = 0.f;
            float sum0 = 0.f, sum1 = 0.f;

            #pragma unroll 1
            for (int sub = 0; sub < 4; sub++) {      // 64-cluster sub-chunks
                const u32 o1 = (u32)sub * 8192;      // 64 clusters * 128B
                const u32 o2 = (u32)sub * 128;       // 64 clusters * 2B (in C^T rows)
                float S[8][4];
                #pragma unroll
                for (int n = 0; n < 8; n++)
                    #pragma unroll
                    for (int e = 0; e < 4; e++) S[n][e] = 0.f;

                // GEMM1: S = X @ C^T (3-term split); pure LDS+HMMA inner loop
                #pragma unroll
                for (int s = 0; s < 4; s++) {
                    const u32 a0 = g1[s][0] + o1;
                    const u32 a1 = g1[s][1] + o1;
                    #pragma unroll
                    for (int nb = 0; nb < 8; nb++) {
                        const u32 b0h = lds32(a0 + nb * 1024);
                        const u32 b1h = lds32(a1 + nb * 1024);
                        const u32 b0l = lds32(a0 + nb * 1024 + 32768);
                        const u32 b1l = lds32(a1 + nb * 1024 + 32768);
                        mma16816(S[nb], Ah[s], b0h, b1h);
                        mma16816(S[nb], Ah[s], b0l, b1l);
                        mma16816(S[nb], Al[s], b0h, b1h);
                    }
                }

                // epilogue: logits -> weights
                #pragma unroll
                for (int nb = 0; nb < 8; nb++) {
                    const int coll = sub * 64 + nb * 8 + 2 * tg;
                    const float2 bb = *reinterpret_cast<const float2*>(smem + SM_BIAS + coll * 4);
                    S[nb][0] = ex2f(fmaf(S[nb][0], SC, -bb.x));
                    S[nb][1] = ex2f(fmaf(S[nb][1], SC, -bb.y));
                    S[nb][2] = ex2f(fmaf(S[nb][2], SC, -bb.x));
                    S[nb][3] = ex2f(fmaf(S[nb][3], SC, -bb.y));
                    sum0 += S[nb][0] + S[nb][1];
                    sum1 += S[nb][2] + S[nb][3];
                }

                // GEMM2: O += W @ C, A = W via accum->A chaining, B from feat-major C^T
                #pragma unroll
                for (int t = 0; t < 4; t++) {
                    u32 Wh[4], Wl[4];
                    Wh[0] = bf2r(S[2*t][0],   S[2*t][1],   Wl[0]);
                    Wh[1] = bf2r(S[2*t][2],   S[2*t][3],   Wl[1]);
                    Wh[2] = bf2r(S[2*t+1][0], S[2*t+1][1], Wl[2]);
                    Wh[3] = bf2r(S[2*t+1][2], S[2*t+1][3], Wl[3]);
                    const u32 a0 = g2[t][0] + o2;
                    const u32 a1 = g2[t][1] + o2;
                    #pragma unroll
                    for (int nb2 = 0; nb2 < 8; nb2++) {
                        const u32 b0h = lds32(a0 + nb2 * 4096);
                        const u32 b1h = lds32(a1 + nb2 * 4096);
                        const u32 b0l = lds32(a0 + nb2 * 4096 + 32768);
                        const u32 b1l = lds32(a1 + nb2 * 4096 + 32768);
                        mma16816(O[nb2], Wh, b0h, b1h);
                        mma16816(O[nb2], Wh, b0l, b1l);
                        mma16816(O[nb2], Wl, b0h, b1h);
                    }
                }
            }

            // row sums across the 4 lanes of each row group
            sum0 += __shfl_xor_sync(0xFFFFFFFF, sum0, 1);
            sum0 += __shfl_xor_sync(0xFFFFFFFF, sum0, 2);
            sum1 += __shfl_xor_sync(0xFFFFFFFF, sum1, 1);
            sum1 += __shfl_xor_sync(0xFFFFFFFF, sum1, 2);

            float* op = out + ((size_t)tile * TILE_M) * D_FEAT;
            const int r0 = m0 + gid;
            const int r1 = r0 + 8;
            float* ss = reinterpret_cast<float*>(smem + SM_SSUM) + tloc * TILE_M;

            if (h == 0) {
                if (tg == 0) { ss[r0] = sum0; ss[r1] = sum1; }
                #pragma unroll
                for (int n = 0; n < 8; n++) {
                    const int col = 8 * n + 2 * tg;
                    *reinterpret_cast<float2*>(op + r0 * D_FEAT + col) = make_float2(O[n][0], O[n][1]);
                    *reinterpret_cast<float2*>(op + r1 * D_FEAT + col) = make_float2(O[n][2], O[n][3]);
                }
            } else {
                const float inv0 = __frcp_rn(sum0 + ss[r0]);
                const float inv1 = __frcp_rn(sum1 + ss[r1]);
                #pragma unroll
                for (int n = 0; n < 8; n++) {
                    const int col = 8 * n + 2 * tg;
                    float2 p0 = *reinterpret_cast<float2*>(op + r0 * D_FEAT + col);
                    float2 p1 = *reinterpret_cast<float2*>(op + r1 * D_FEAT + col);
                    *reinterpret_cast<float2*>(op + r0 * D_FEAT + col) =
                        make_float2((p0.x + O[n][0]) * inv0, (p0.y + O[n][1]) * inv0);
                    *reinterpret_cast<float2*>(op + r1 * D_FEAT + col) =
                        make_float2((p1.x + O[n][2]) * inv1, (p1.y + O[n][3]) * inv1);
                }
            }
        }
    }
}

extern "C" void kernel_launch(void* const* d_in, const int* in_sizes, int n_in,
                              void* d_out, int out_size)
{
    const float* x = (const float*)d_in[0];
    const float* centroids = (const float*)d_in[1];
    float* out = (float*)d_out;

    const int n_points = in_sizes[0] / D_FEAT;   // 131072
    const int n_tiles = n_points / TILE_M;       // 1024

    static bool attr_set = false;
    if (!attr_set) {
        cudaFuncSetAttribute(kmeans_hmma3_kernel,
                             cudaFuncAttributeMaxDynamicSharedMemorySize, SM_TOTAL);
        attr_set = true;
    }

    const int grid = (n_tiles < 148) ? n_tiles : 148;
    kmeans_hmma3_kernel<<<grid, NTHREADS, SM_TOTAL>>>(x, centroids, out, n_tiles);
}